// round 9
// baseline (speedup 1.0000x reference)
#include <cuda_runtime.h>
#include <cstdint>

#define B_ 16
#define N_ 577
#define H_ 12
#define D_ 64
#define C_ 768
#define BH_ 192
#define M_ 9232
#define KTS 640       // vT row stride (zero-padded cols 577..639)
#define SST 640       // score row stride (zero-padded cols 577..639)
#define SCALE_ 0.125f

// ---------------- device scratch (no cudaMalloc allowed) ----------------
__device__ float g_q[BH_ * N_ * D_];                 // (bh, n, d)
__device__ float g_k[BH_ * N_ * D_];                 // (bh, n, d)
__device__ float g_vT[BH_ * D_ * KTS];               // (bh, d, m) zero-padded
__device__ float g_S[(size_t)(BH_ * N_ + 64) * SST]; // scores, then exp(P)
__device__ float g_pxy[BH_ * N_ * 104];              // px[0:52), py[52:104)
__device__ float g_bins[BH_ * N_ * 104];             // binx[0:52), biny[52:104)
__device__ float g_rowsum[BH_ * N_ + 64];
__device__ float g_ao[M_ * C_];                      // attention out (b*n, c)

// ---------------- tf32 helpers (base sm_103 target) ----------------
__device__ __forceinline__ uint32_t f2tf(float f) {
  uint32_t r;
  asm("cvt.rna.tf32.f32 %0, %1;" : "=r"(r) : "f"(f));
  return r;
}
__device__ __forceinline__ void mma16n8k8(float* d, const uint32_t* a,
                                          uint32_t b0, uint32_t b1) {
  asm volatile(
      "mma.sync.aligned.m16n8k8.row.col.f32.tf32.tf32.f32 "
      "{%0,%1,%2,%3}, {%4,%5,%6,%7}, {%8,%9}, {%0,%1,%2,%3};"
      : "+f"(d[0]), "+f"(d[1]), "+f"(d[2]), "+f"(d[3])
      : "r"(a[0]), "r"(a[1]), "r"(a[2]), "r"(a[3]), "r"(b0), "r"(b1));
}
__device__ __forceinline__ uint4 cvt4u(float4 v) {
  return make_uint4(f2tf(v.x), f2tf(v.y), f2tf(v.z), f2tf(v.w));
}

// ======== tf32 mma.sync GEMM: C[m,c] = sum_k A[m,k] * W[c,k] ========
// 128x128 CTA tile, 256 threads, BK=64 (12 staging rounds), stride-68 smem.
// MODE 0: A = x, scatter-store q/k natural + vT transposed
// MODE 1: A = g_ao, row-major store into out
#define MG_SMEM (2 * 128 * 68 * 4)  // 69632 B

template <int MODE>
__global__ __launch_bounds__(256, 2)
void mma_gemm_kernel(const float* __restrict__ Ain, const float* __restrict__ W,
                     float* __restrict__ out) {
  extern __shared__ uint32_t smu[];
  uint32_t* As = smu;              // [128][68]
  uint32_t* Bs = smu + 128 * 68;   // [128][68]
  const float* A = (MODE == 0) ? Ain : (const float*)g_ao;
  const int row0 = blockIdx.y * 128, col0 = blockIdx.x * 128;
  const int tid = threadIdx.x, lane = tid & 31, wid = tid >> 5;
  const int warpM = wid & 3, warpN = wid >> 2;
  const int g = lane >> 2, tg = lane & 3;

  float acc[16][4];
#pragma unroll
  for (int i = 0; i < 16; i++)
#pragma unroll
    for (int j = 0; j < 4; j++) acc[i][j] = 0.f;

  const int lr = tid >> 1;           // 0..127
  const int lk = (tid & 1) * 32;     // 0 / 32
  const bool aval = (row0 + lr) < M_;
  const float* ap = A + (size_t)(row0 + lr) * C_ + lk;
  const float* bp = W + (size_t)(col0 + lr) * C_ + lk;
  const uint32_t soff = (uint32_t)(lr * 68 + lk);

  for (int kt = 0; kt < 12; kt++) {
    __syncthreads();
#pragma unroll
    for (int i = 0; i < 8; i++) {
      float4 va = aval ? *(const float4*)(ap + kt * 64 + i * 4)
                       : make_float4(0.f, 0.f, 0.f, 0.f);
      float4 vb = *(const float4*)(bp + kt * 64 + i * 4);
      *(uint4*)&As[soff + i * 4] = cvt4u(va);
      *(uint4*)&Bs[soff + i * 4] = cvt4u(vb);
    }
    __syncthreads();
#pragma unroll
    for (int s = 0; s < 8; s++) {
      const int kk = s * 8;
      uint32_t a[2][4];
#pragma unroll
      for (int mt = 0; mt < 2; mt++) {
        const int r = warpM * 32 + mt * 16;
        a[mt][0] = As[(r + g) * 68 + kk + tg];
        a[mt][1] = As[(r + g + 8) * 68 + kk + tg];
        a[mt][2] = As[(r + g) * 68 + kk + tg + 4];
        a[mt][3] = As[(r + g + 8) * 68 + kk + tg + 4];
      }
#pragma unroll
      for (int nt = 0; nt < 8; nt++) {
        const int c = warpN * 64 + nt * 8;
        uint32_t b0 = Bs[(c + g) * 68 + kk + tg];
        uint32_t b1 = Bs[(c + g) * 68 + kk + tg + 4];
        mma16n8k8(acc[nt], a[0], b0, b1);
        mma16n8k8(acc[8 + nt], a[1], b0, b1);
      }
    }
  }

  if (MODE == 1) {
#pragma unroll
    for (int mt = 0; mt < 2; mt++)
#pragma unroll
      for (int half = 0; half < 2; half++) {
        const int m = row0 + warpM * 32 + mt * 16 + g + half * 8;
        if (m >= M_) continue;
        float* dst = out + (size_t)m * C_ + col0 + warpN * 64 + 2 * tg;
#pragma unroll
        for (int nt = 0; nt < 8; nt++)
          *(float2*)(dst + nt * 8) = make_float2(acc[mt * 8 + nt][half * 2],
                                                 acc[mt * 8 + nt][half * 2 + 1]);
      }
  } else {
    const int cg = col0 + warpN * 64;   // multiple of 64 -> one head per warp
    const int which = cg / C_;          // 0=q 1=k 2=v
    const int h = (cg % C_) / D_;
#pragma unroll
    for (int mt = 0; mt < 2; mt++)
#pragma unroll
      for (int half = 0; half < 2; half++) {
        const int m = row0 + warpM * 32 + mt * 16 + g + half * 8;
        if (m >= M_) continue;
        const int b = m / N_, n = m % N_;
        const int bh = b * H_ + h;
        if (which == 2) {
          const size_t base = (size_t)bh * D_ * KTS + n;
          const int d0 = 2 * tg;
#pragma unroll
          for (int nt = 0; nt < 8; nt++) {
            g_vT[base + (size_t)(d0 + nt * 8) * KTS] = acc[mt * 8 + nt][half * 2];
            g_vT[base + (size_t)(d0 + nt * 8 + 1) * KTS] =
                acc[mt * 8 + nt][half * 2 + 1];
          }
        } else {
          float* dst = (which == 0 ? g_q : g_k) + ((size_t)bh * N_ + n) * D_ + 2 * tg;
#pragma unroll
          for (int nt = 0; nt < 8; nt++)
            *(float2*)(dst + nt * 8) =
                make_float2(acc[mt * 8 + nt][half * 2],
                            acc[mt * 8 + nt][half * 2 + 1]);
        }
      }
  }
}

// ---------------- px/py projection ----------------
__global__ __launch_bounds__(256)
void pxpy_kernel(const float* __restrict__ qxe, const float* __restrict__ qye) {
  __shared__ float qs[64][65];
  __shared__ float ex[50][33];
  __shared__ float ey[50][33];
  const int bh = blockIdx.y;
  const int row0 = blockIdx.x * 64;
  const int tid = threadIdx.x;
  for (int f = tid; f < 64 * 16; f += 256) {
    int r = f >> 4, c4 = (f & 15) << 2;
    int n = row0 + r;
    float4 v = (n < N_) ? *(const float4*)(g_q + ((size_t)bh * N_ + n) * D_ + c4)
                        : make_float4(0.f, 0.f, 0.f, 0.f);
    qs[r][c4 + 0] = v.x; qs[r][c4 + 1] = v.y;
    qs[r][c4 + 2] = v.z; qs[r][c4 + 3] = v.w;
  }
  for (int f = tid; f < 1600; f += 256) {
    ex[f >> 5][f & 31] = qxe[f];
    ey[f >> 5][f & 31] = qye[f];
  }
  __syncthreads();
  for (int idx = tid; idx < 64 * 50; idx += 256) {
    int r = idx / 50, t = idx % 50;
    float ax = 0.f, ay = 0.f;
#pragma unroll
    for (int d = 0; d < 32; d++) {
      ax += qs[r][d] * ex[t][d];
      ay += qs[r][32 + d] * ey[t][d];
    }
    int n = row0 + r;
    if (n < N_) {
      float* p = g_pxy + ((size_t)bh * N_ + n) * 104;
      p[t] = ax;
      p[52 + t] = ay;
    }
  }
}

// ---------------- scores via mma: S[bh,n,m] = q·k (single staging round) ----
#define SC_SMEM (2 * 128 * 68 * 4)
__global__ __launch_bounds__(256, 2)
void scores_mma_kernel() {
  extern __shared__ uint32_t smu[];
  uint32_t* As = smu;
  uint32_t* Bs = smu + 128 * 68;
  const int bh = blockIdx.z;
  const int row0 = blockIdx.y * 128, col0 = blockIdx.x * 128;
  const int tid = threadIdx.x, lane = tid & 31, wid = tid >> 5;
  const int warpM = wid & 3, warpN = wid >> 2;
  const int g = lane >> 2, tg = lane & 3;

  float acc[16][4];
#pragma unroll
  for (int i = 0; i < 16; i++)
#pragma unroll
    for (int j = 0; j < 4; j++) acc[i][j] = 0.f;

  const int lr = tid >> 1;
  const int lk = (tid & 1) * 32;
  const bool aval = (row0 + lr) < N_;
  const bool bval = (col0 + lr) < N_;
  const float* ap = g_q + ((size_t)bh * N_ + row0 + lr) * D_ + lk;
  const float* bp = g_k + ((size_t)bh * N_ + col0 + lr) * D_ + lk;
  const uint32_t soff = (uint32_t)(lr * 68 + lk);

#pragma unroll
  for (int i = 0; i < 8; i++) {
    float4 va = aval ? *(const float4*)(ap + i * 4)
                     : make_float4(0.f, 0.f, 0.f, 0.f);
    float4 vb = bval ? *(const float4*)(bp + i * 4)
                     : make_float4(0.f, 0.f, 0.f, 0.f);
    *(uint4*)&As[soff + i * 4] = cvt4u(va);
    *(uint4*)&Bs[soff + i * 4] = cvt4u(vb);
  }
  __syncthreads();

#pragma unroll
  for (int s = 0; s < 8; s++) {
    const int kk = s * 8;
    uint32_t a[2][4];
#pragma unroll
    for (int mt = 0; mt < 2; mt++) {
      const int r = warpM * 32 + mt * 16;
      a[mt][0] = As[(r + g) * 68 + kk + tg];
      a[mt][1] = As[(r + g + 8) * 68 + kk + tg];
      a[mt][2] = As[(r + g) * 68 + kk + tg + 4];
      a[mt][3] = As[(r + g + 8) * 68 + kk + tg + 4];
    }
#pragma unroll
    for (int nt = 0; nt < 8; nt++) {
      const int c = warpN * 64 + nt * 8;
      uint32_t b0 = Bs[(c + g) * 68 + kk + tg];
      uint32_t b1 = Bs[(c + g) * 68 + kk + tg + 4];
      mma16n8k8(acc[nt], a[0], b0, b1);
      mma16n8k8(acc[8 + nt], a[1], b0, b1);
    }
  }

#pragma unroll
  for (int mt = 0; mt < 2; mt++)
#pragma unroll
    for (int half = 0; half < 2; half++) {
      const int n = row0 + warpM * 32 + mt * 16 + g + half * 8;
      if (n >= N_) continue;
      float* dst = g_S + ((size_t)bh * N_ + n) * SST + col0 + warpN * 64 + 2 * tg;
#pragma unroll
      for (int nt = 0; nt < 8; nt++)
        *(float2*)(dst + nt * 8) = make_float2(acc[mt * 8 + nt][half * 2],
                                               acc[mt * 8 + nt][half * 2 + 1]);
    }
}

// ---------------- softmax + bias + analytic binning ----------------
__global__ __launch_bounds__(256)
void softmax_kernel() {
  __shared__ float st[8][64];
  const int w = threadIdx.x >> 5, lane = threadIdx.x & 31;
  const int row = blockIdx.x * 8 + w;
  if (row >= BH_ * N_) return;
  const int n = row % N_;
  float* Srow = g_S + (size_t)row * SST;
  const float* pxy = g_pxy + (size_t)row * 104;
  const bool cls = (n == 0);
  const int xcol = cls ? 0 : (n - 1) % 24;
  const int yrow = cls ? 0 : (n - 1) / 24;

  float pxl = 0.f, pyl = 0.f;
  if (lane < 24) {
    pxl = cls ? pxy[0] : pxy[25 + lane - xcol];
    pyl = cls ? pxy[52] : pxy[52 + 25 + lane - yrow];
  }
  const float l0 = (Srow[0] + pxy[0] + pxy[52]) * SCALE_;
  float mx = l0;
  float lg[24];
#pragma unroll
  for (int k = 0; k < 24; k++) {
    float pyk = __shfl_sync(0xffffffffu, pyl, k);
    float s = -1e30f;
    if (lane < 24) s = (Srow[1 + 24 * k + lane] + pxl + pyk) * SCALE_;
    lg[k] = s;
    mx = fmaxf(mx, s);
  }
#pragma unroll
  for (int o = 16; o; o >>= 1) mx = fmaxf(mx, __shfl_xor_sync(0xffffffffu, mx, o));

  float colsum = 0.f, total = 0.f, binyreg = 0.f;
  const float e0 = __expf(l0 - mx);
#pragma unroll
  for (int k = 0; k < 24; k++) {
    float e = 0.f;
    if (lane < 24) {
      e = __expf(lg[k] - mx);
      Srow[1 + 24 * k + lane] = e;
    }
    colsum += e;
    float rs = e;
#pragma unroll
    for (int o = 16; o; o >>= 1) rs += __shfl_xor_sync(0xffffffffu, rs, o);
    total += rs;
    if (lane == k) binyreg = rs;
  }
  if (lane == 0) Srow[0] = e0;
  Srow[577 + lane] = 0.f;  // zero-pad cols 577..608
  Srow[608 + lane] = 0.f;  // zero-pad cols 608..639 (BK=64 AV staging)
  total += e0;
  if (lane == 0) g_rowsum[row] = total;

  st[w][lane] = colsum;
  st[w][32 + lane] = binyreg;
  __syncwarp();
  float* brow = g_bins + (size_t)row * 104;
  for (int t = lane; t < 104; t += 32) {
    float v = 0.f;
    if (cls) {
      if (t == 0 || t == 52) v = total;
    } else if (t == 0 || t == 52) {
      v = e0;
    } else if (t < 52) {
      int c = t - 25 + xcol;
      if (c >= 0 && c < 24) v = st[w][c];
    } else {
      int k = (t - 52) - 25 + yrow;
      if (k >= 0 && k < 24) v = st[w][32 + k];
    }
    brow[t] = v;
  }
}

// ---------------- AV via mma (BK=64) + bias-mma + normalize ----------------
#define AV_SMEM 77312
__global__ __launch_bounds__(256, 2)
void av_mma_kernel(const float* __restrict__ vxe, const float* __restrict__ vye) {
  extern __shared__ uint32_t dsm[];
  uint32_t* As = dsm;              // [128][68] P tile
  uint32_t* Bs = dsm + 128 * 68;   // [64][68] vT tile
  const int bh = blockIdx.y, row0 = blockIdx.x * 128;
  const int tid = threadIdx.x, lane = tid & 31, wid = tid >> 5;
  const int g = lane >> 2, tg = lane & 3;

  float acc[8][4];
#pragma unroll
  for (int i = 0; i < 8; i++)
#pragma unroll
    for (int j = 0; j < 4; j++) acc[i][j] = 0.f;

  const int lr = tid >> 1, lk = (tid & 1) * 32;
  const float* ap = g_S + ((size_t)bh * N_ + row0 + lr) * SST + lk;
  const int vr = tid >> 2, vc = (tid & 3) * 16;
  const float* vp = g_vT + (size_t)bh * D_ * KTS + (size_t)vr * KTS + vc;
  const int wr = wid * 16;
  const uint32_t aoff = (uint32_t)(lr * 68 + lk);
  const uint32_t boff = (uint32_t)(vr * 68 + vc);

  for (int kt = 0; kt < 10; kt++) {
    const int k0 = kt * 64;
    __syncthreads();
#pragma unroll
    for (int i = 0; i < 8; i++) {
      float4 va = *(const float4*)(ap + k0 + i * 4);
      *(uint4*)&As[aoff + i * 4] = cvt4u(va);
    }
#pragma unroll
    for (int i = 0; i < 4; i++) {
      float4 vb = *(const float4*)(vp + k0 + i * 4);
      *(uint4*)&Bs[boff + i * 4] = cvt4u(vb);
    }
    __syncthreads();
#pragma unroll
    for (int s = 0; s < 8; s++) {
      const int kk = s * 8;
      uint32_t a[4];
      a[0] = As[(wr + g) * 68 + kk + tg];
      a[1] = As[(wr + g + 8) * 68 + kk + tg];
      a[2] = As[(wr + g) * 68 + kk + tg + 4];
      a[3] = As[(wr + g + 8) * 68 + kk + tg + 4];
#pragma unroll
      for (int nt = 0; nt < 8; nt++) {
        uint32_t b0 = Bs[(nt * 8 + g) * 68 + kk + tg];
        uint32_t b1 = Bs[(nt * 8 + g) * 68 + kk + tg + 4];
        mma16n8k8(acc[nt], a, b0, b1);
      }
    }
  }
  __syncthreads();

  // ---- bias phase: bins (128x52) x emb^T (32x52) accumulated via mma ----
  uint32_t* bxs = dsm;                         // [128][60]
  uint32_t* bys = dsm + 128 * 60;              // [128][60]
  uint32_t* exs = dsm + 2 * 128 * 60;          // [32][60]
  uint32_t* eys = dsm + 2 * 128 * 60 + 32 * 60;
  float* invs = (float*)(dsm + 2 * 128 * 60 + 2 * 32 * 60);  // [128]

  for (int f = tid; f < 128 * 60; f += 256) {
    int r = f / 60, t = f % 60;
    int n = row0 + r;
    float vx = 0.f, vy = 0.f;
    if (t < 52 && n < N_) {
      const float* p = g_bins + ((size_t)bh * N_ + n) * 104;
      vx = p[t];
      vy = p[52 + t];
    }
    bxs[r * 60 + t] = f2tf(vx);
    bys[r * 60 + t] = f2tf(vy);
  }
  for (int f = tid; f < 32 * 60; f += 256) {
    int c = f / 60, t = f % 60;
    float ax = 0.f, ay = 0.f;
    if (t < 50) {
      ax = vxe[t * 32 + c];
      ay = vye[t * 32 + c];
    }
    exs[f] = f2tf(ax);
    eys[f] = f2tf(ay);
  }
  for (int f = tid; f < 128; f += 256) {
    int n = row0 + f;
    invs[f] = (n < N_) ? 1.f / g_rowsum[(size_t)bh * N_ + n] : 1.f;
  }
  __syncthreads();

#pragma unroll
  for (int s = 0; s < 7; s++) {
    const int kk = s * 8;
    uint32_t ax[4], ay[4];
    ax[0] = bxs[(wr + g) * 60 + kk + tg];
    ax[1] = bxs[(wr + g + 8) * 60 + kk + tg];
    ax[2] = bxs[(wr + g) * 60 + kk + tg + 4];
    ax[3] = bxs[(wr + g + 8) * 60 + kk + tg + 4];
    ay[0] = bys[(wr + g) * 60 + kk + tg];
    ay[1] = bys[(wr + g + 8) * 60 + kk + tg];
    ay[2] = bys[(wr + g) * 60 + kk + tg + 4];
    ay[3] = bys[(wr + g + 8) * 60 + kk + tg + 4];
#pragma unroll
    for (int nt = 0; nt < 4; nt++) {
      uint32_t b0 = exs[(nt * 8 + g) * 60 + kk + tg];
      uint32_t b1 = exs[(nt * 8 + g) * 60 + kk + tg + 4];
      mma16n8k8(acc[nt], ax, b0, b1);
    }
#pragma unroll
    for (int nt = 0; nt < 4; nt++) {
      uint32_t b0 = eys[(nt * 8 + g) * 60 + kk + tg];
      uint32_t b1 = eys[(nt * 8 + g) * 60 + kk + tg + 4];
      mma16n8k8(acc[4 + nt], ay, b0, b1);
    }
  }

  // ---- normalize + store ----
  const float i0 = invs[wr + g], i1 = invs[wr + g + 8];
  const int b = bh / H_, h = bh % H_;
#pragma unroll
  for (int half = 0; half < 2; half++) {
    const int n = row0 + wr + g + half * 8;
    if (n >= N_) continue;
    const float inv = half ? i1 : i0;
    float* dst = g_ao + ((size_t)b * N_ + n) * C_ + h * D_ + 2 * tg;
#pragma unroll
    for (int nt = 0; nt < 8; nt++)
      *(float2*)(dst + nt * 8) = make_float2(acc[nt][half * 2] * inv,
                                             acc[nt][half * 2 + 1] * inv);
  }
}

// ---------------- launch ----------------
extern "C" void kernel_launch(void* const* d_in, const int* in_sizes, int n_in,
                              void* d_out, int out_size) {
  const float* x = (const float*)d_in[0];
  const float* qkv_w = (const float*)d_in[1];
  const float* proj_w = (const float*)d_in[2];
  const float* qxe = (const float*)d_in[3];
  const float* qye = (const float*)d_in[4];
  const float* vxe = (const float*)d_in[5];
  const float* vye = (const float*)d_in[6];
  float* out = (float*)d_out;

  cudaFuncSetAttribute(mma_gemm_kernel<0>,
                       cudaFuncAttributeMaxDynamicSharedMemorySize, MG_SMEM);
  cudaFuncSetAttribute(mma_gemm_kernel<1>,
                       cudaFuncAttributeMaxDynamicSharedMemorySize, MG_SMEM);
  cudaFuncSetAttribute(scores_mma_kernel,
                       cudaFuncAttributeMaxDynamicSharedMemorySize, SC_SMEM);
  cudaFuncSetAttribute(av_mma_kernel, cudaFuncAttributeMaxDynamicSharedMemorySize,
                       AV_SMEM);

  // QKV projection (tf32 tensor cores, BK=64)
  mma_gemm_kernel<0><<<dim3(18, 73), 256, MG_SMEM>>>(x, qkv_w, nullptr);

  pxpy_kernel<<<dim3(10, BH_), 256>>>(qxe, qye);

  // scores (tf32 tensor cores, single staging round)
  scores_mma_kernel<<<dim3(5, 5, BH_), 256, SC_SMEM>>>();

  softmax_kernel<<<(BH_ * N_ + 7) / 8, 256>>>();

  // AV + bias (tf32 tensor cores, BK=64)
  av_mma_kernel<<<dim3(5, BH_), 256, AV_SMEM>>>(vxe, vye);

  // Output projection (tf32 tensor cores, BK=64)
  mma_gemm_kernel<1><<<dim3(6, 73), 256, MG_SMEM>>>(nullptr, proj_w, out);
}

// round 11
// speedup vs baseline: 1.4335x; 1.4335x over previous
#include <cuda_runtime.h>
#include <cuda_fp16.h>
#include <cstdint>

#define B_ 16
#define N_ 577
#define H_ 12
#define D_ 64
#define C_ 768
#define BH_ 192
#define M_ 9232
#define KTS 640       // vT row stride (zero-padded cols 577..639)
#define SST 640       // score row stride
#define SCALE_ 0.125f

// ---------------- device scratch (no cudaMalloc allowed) ----------------
__device__ float g_q[BH_ * N_ * D_];                 // (bh, n, d)
__device__ float g_k[BH_ * N_ * D_];                 // (bh, n, d)
__device__ float g_vT[BH_ * D_ * KTS];               // (bh, d, m) zero-padded
__device__ float g_S[(size_t)(BH_ * N_ + 64) * SST]; // scores, then exp(P)
__device__ float g_pxy[BH_ * N_ * 104];              // px[0:52), py[52:104)
__device__ float g_bins[BH_ * N_ * 104];             // binx[0:52), biny[52:104)
__device__ float g_rowsum[BH_ * N_ + 64];
__device__ float g_ao[M_ * C_];                      // attention out (b*n, c)

// ---------------- fp16 mma helpers (base sm_103 target) ----------------
__device__ __forceinline__ uint32_t f2h2(float lo, float hi) {
  __half2 h = __floats2half2_rn(lo, hi);
  return *reinterpret_cast<uint32_t*>(&h);
}
__device__ __forceinline__ uint2 cvt4h(float4 v) {
  return make_uint2(f2h2(v.x, v.y), f2h2(v.z, v.w));
}
// m16n8k16 f16 x f16 -> f32
__device__ __forceinline__ void mmaf16(float* d, const uint32_t* a,
                                       uint32_t b0, uint32_t b1) {
  asm volatile(
      "mma.sync.aligned.m16n8k16.row.col.f32.f16.f16.f32 "
      "{%0,%1,%2,%3}, {%4,%5,%6,%7}, {%8,%9}, {%0,%1,%2,%3};"
      : "+f"(d[0]), "+f"(d[1]), "+f"(d[2]), "+f"(d[3])
      : "r"(a[0]), "r"(a[1]), "r"(a[2]), "r"(a[3]), "r"(b0), "r"(b1));
}

// ======== fp16 mma GEMM: C[m,c] = sum_k A[m,k] * W[c,k] ========
// 128x128 CTA tile, 256 threads, BK=32 (16 half2 words/row, stride 20).
// MODE 0: A = x, scatter-store q/k natural + vT transposed
// MODE 1: A = g_ao, row-major store into out
template <int MODE>
__global__ __launch_bounds__(256)
void mma_gemm_kernel(const float* __restrict__ Ain, const float* __restrict__ W,
                     float* __restrict__ out) {
  __shared__ uint32_t As[128][20];
  __shared__ uint32_t Bs[128][20];
  const float* A = (MODE == 0) ? Ain : (const float*)g_ao;
  const int row0 = blockIdx.y * 128, col0 = blockIdx.x * 128;
  const int tid = threadIdx.x, lane = tid & 31, wid = tid >> 5;
  const int warpM = wid & 3, warpN = wid >> 2;
  const int g = lane >> 2, tg = lane & 3;

  float acc[16][4];
#pragma unroll
  for (int i = 0; i < 16; i++)
#pragma unroll
    for (int j = 0; j < 4; j++) acc[i][j] = 0.f;

  const int lr = tid >> 1;           // 0..127
  const int lkf = (tid & 1) * 16;    // float offset 0 / 16
  const int lkw = (tid & 1) * 8;     // word offset 0 / 8
  const bool aval = (row0 + lr) < M_;
  const float* ap = A + (size_t)(row0 + lr) * C_ + lkf;
  const float* bp = W + (size_t)(col0 + lr) * C_ + lkf;

  for (int k0 = 0; k0 < C_; k0 += 32) {
    __syncthreads();
    {
      float4 a0, a1, a2, a3;
      if (aval) {
        a0 = *(const float4*)(ap + k0);
        a1 = *(const float4*)(ap + k0 + 4);
        a2 = *(const float4*)(ap + k0 + 8);
        a3 = *(const float4*)(ap + k0 + 12);
      } else {
        a0 = make_float4(0.f, 0.f, 0.f, 0.f);
        a1 = a0; a2 = a0; a3 = a0;
      }
      float4 b0 = *(const float4*)(bp + k0);
      float4 b1 = *(const float4*)(bp + k0 + 4);
      float4 b2 = *(const float4*)(bp + k0 + 8);
      float4 b3 = *(const float4*)(bp + k0 + 12);
      uint2 wa0 = cvt4h(a0), wa1 = cvt4h(a1), wa2 = cvt4h(a2), wa3 = cvt4h(a3);
      uint2 wb0 = cvt4h(b0), wb1 = cvt4h(b1), wb2 = cvt4h(b2), wb3 = cvt4h(b3);
      *(uint4*)&As[lr][lkw] = make_uint4(wa0.x, wa0.y, wa1.x, wa1.y);
      *(uint4*)&As[lr][lkw + 4] = make_uint4(wa2.x, wa2.y, wa3.x, wa3.y);
      *(uint4*)&Bs[lr][lkw] = make_uint4(wb0.x, wb0.y, wb1.x, wb1.y);
      *(uint4*)&Bs[lr][lkw + 4] = make_uint4(wb2.x, wb2.y, wb3.x, wb3.y);
    }
    __syncthreads();
#pragma unroll
    for (int s = 0; s < 2; s++) {
      const int kw = s * 8;
      uint32_t a[2][4];
#pragma unroll
      for (int mt = 0; mt < 2; mt++) {
        const int r = warpM * 32 + mt * 16;
        a[mt][0] = As[r + g][kw + tg];
        a[mt][1] = As[r + g + 8][kw + tg];
        a[mt][2] = As[r + g][kw + tg + 4];
        a[mt][3] = As[r + g + 8][kw + tg + 4];
      }
#pragma unroll
      for (int nt = 0; nt < 8; nt++) {
        const int c = warpN * 64 + nt * 8;
        uint32_t b0 = Bs[c + g][kw + tg];
        uint32_t b1 = Bs[c + g][kw + tg + 4];
        mmaf16(acc[nt], a[0], b0, b1);
        mmaf16(acc[8 + nt], a[1], b0, b1);
      }
    }
  }

  if (MODE == 1) {
#pragma unroll
    for (int mt = 0; mt < 2; mt++)
#pragma unroll
      for (int half = 0; half < 2; half++) {
        const int m = row0 + warpM * 32 + mt * 16 + g + half * 8;
        if (m >= M_) continue;
        float* dst = out + (size_t)m * C_ + col0 + warpN * 64 + 2 * tg;
#pragma unroll
        for (int nt = 0; nt < 8; nt++)
          *(float2*)(dst + nt * 8) = make_float2(acc[mt * 8 + nt][half * 2],
                                                 acc[mt * 8 + nt][half * 2 + 1]);
      }
  } else {
    const int cg = col0 + warpN * 64;   // multiple of 64 -> one head per warp
    const int which = cg / C_;          // 0=q 1=k 2=v
    const int h = (cg % C_) / D_;
#pragma unroll
    for (int mt = 0; mt < 2; mt++)
#pragma unroll
      for (int half = 0; half < 2; half++) {
        const int m = row0 + warpM * 32 + mt * 16 + g + half * 8;
        if (m >= M_) continue;
        const int b = m / N_, n = m % N_;
        const int bh = b * H_ + h;
        if (which == 2) {
          const size_t base = (size_t)bh * D_ * KTS + n;
          const int d0 = 2 * tg;
#pragma unroll
          for (int nt = 0; nt < 8; nt++) {
            g_vT[base + (size_t)(d0 + nt * 8) * KTS] = acc[mt * 8 + nt][half * 2];
            g_vT[base + (size_t)(d0 + nt * 8 + 1) * KTS] =
                acc[mt * 8 + nt][half * 2 + 1];
          }
        } else {
          float* dst = (which == 0 ? g_q : g_k) + ((size_t)bh * N_ + n) * D_ + 2 * tg;
#pragma unroll
          for (int nt = 0; nt < 8; nt++)
            *(float2*)(dst + nt * 8) =
                make_float2(acc[mt * 8 + nt][half * 2],
                            acc[mt * 8 + nt][half * 2 + 1]);
        }
      }
  }
}

// ---------------- px/py projection ----------------
__global__ __launch_bounds__(256)
void pxpy_kernel(const float* __restrict__ qxe, const float* __restrict__ qye) {
  __shared__ float qs[64][65];
  __shared__ float ex[50][33];
  __shared__ float ey[50][33];
  const int bh = blockIdx.y;
  const int row0 = blockIdx.x * 64;
  const int tid = threadIdx.x;
  for (int f = tid; f < 64 * 16; f += 256) {
    int r = f >> 4, c4 = (f & 15) << 2;
    int n = row0 + r;
    float4 v = (n < N_) ? *(const float4*)(g_q + ((size_t)bh * N_ + n) * D_ + c4)
                        : make_float4(0.f, 0.f, 0.f, 0.f);
    qs[r][c4 + 0] = v.x; qs[r][c4 + 1] = v.y;
    qs[r][c4 + 2] = v.z; qs[r][c4 + 3] = v.w;
  }
  for (int f = tid; f < 1600; f += 256) {
    ex[f >> 5][f & 31] = qxe[f];
    ey[f >> 5][f & 31] = qye[f];
  }
  __syncthreads();
  for (int idx = tid; idx < 64 * 50; idx += 256) {
    int r = idx / 50, t = idx % 50;
    float ax = 0.f, ay = 0.f;
#pragma unroll
    for (int d = 0; d < 32; d++) {
      ax += qs[r][d] * ex[t][d];
      ay += qs[r][32 + d] * ey[t][d];
    }
    int n = row0 + r;
    if (n < N_) {
      float* p = g_pxy + ((size_t)bh * N_ + n) * 104;
      p[t] = ax;
      p[52 + t] = ay;
    }
  }
}

// ---------------- scores via fp16 mma: S[bh,n,m] = q·k ----------------
// K=64 = 32 words/row, stride 36, single staging round, 4 k16-steps.
// Each of the 2 threads/row stages 32 floats = 16 words (8 x float4).
__global__ __launch_bounds__(256)
void scores_mma_kernel() {
  __shared__ uint32_t As[128][36];
  __shared__ uint32_t Bs[128][36];
  const int bh = blockIdx.z;
  const int row0 = blockIdx.y * 128, col0 = blockIdx.x * 128;
  const int tid = threadIdx.x, lane = tid & 31, wid = tid >> 5;
  const int warpM = wid & 3, warpN = wid >> 2;
  const int g = lane >> 2, tg = lane & 3;

  float acc[16][4];
#pragma unroll
  for (int i = 0; i < 16; i++)
#pragma unroll
    for (int j = 0; j < 4; j++) acc[i][j] = 0.f;

  const int lr = tid >> 1;
  const int lkf = (tid & 1) * 32;    // float offset 0 / 32
  const int lkw = (tid & 1) * 16;    // word offset 0 / 16
  const bool aval = (row0 + lr) < N_;
  const bool bval = (col0 + lr) < N_;
  const float* ap = g_q + ((size_t)bh * N_ + row0 + lr) * D_ + lkf;
  const float* bp = g_k + ((size_t)bh * N_ + col0 + lr) * D_ + lkf;

#pragma unroll
  for (int i = 0; i < 8; i++) {   // 8 x float4 = 32 floats = 16 words
    float4 va = aval ? *(const float4*)(ap + i * 4)
                     : make_float4(0.f, 0.f, 0.f, 0.f);
    float4 vb = bval ? *(const float4*)(bp + i * 4)
                     : make_float4(0.f, 0.f, 0.f, 0.f);
    uint2 wa = cvt4h(va), wb = cvt4h(vb);
    As[lr][lkw + i * 2] = wa.x;
    As[lr][lkw + i * 2 + 1] = wa.y;
    Bs[lr][lkw + i * 2] = wb.x;
    Bs[lr][lkw + i * 2 + 1] = wb.y;
  }
  __syncthreads();

#pragma unroll
  for (int s = 0; s < 4; s++) {
    const int kw = s * 8;
    uint32_t a[2][4];
#pragma unroll
    for (int mt = 0; mt < 2; mt++) {
      const int r = warpM * 32 + mt * 16;
      a[mt][0] = As[r + g][kw + tg];
      a[mt][1] = As[r + g + 8][kw + tg];
      a[mt][2] = As[r + g][kw + tg + 4];
      a[mt][3] = As[r + g + 8][kw + tg + 4];
    }
#pragma unroll
    for (int nt = 0; nt < 8; nt++) {
      const int c = warpN * 64 + nt * 8;
      uint32_t b0 = Bs[c + g][kw + tg];
      uint32_t b1 = Bs[c + g][kw + tg + 4];
      mmaf16(acc[nt], a[0], b0, b1);
      mmaf16(acc[8 + nt], a[1], b0, b1);
    }
  }

#pragma unroll
  for (int mt = 0; mt < 2; mt++)
#pragma unroll
    for (int half = 0; half < 2; half++) {
      const int n = row0 + warpM * 32 + mt * 16 + g + half * 8;
      if (n >= N_) continue;
      float* dst = g_S + ((size_t)bh * N_ + n) * SST + col0 + warpN * 64 + 2 * tg;
#pragma unroll
      for (int nt = 0; nt < 8; nt++)
        *(float2*)(dst + nt * 8) = make_float2(acc[mt * 8 + nt][half * 2],
                                               acc[mt * 8 + nt][half * 2 + 1]);
    }
}

// ---------------- softmax + bias + analytic binning ----------------
__global__ __launch_bounds__(256)
void softmax_kernel() {
  __shared__ float st[8][64];
  const int w = threadIdx.x >> 5, lane = threadIdx.x & 31;
  const int row = blockIdx.x * 8 + w;
  if (row >= BH_ * N_) return;
  const int n = row % N_;
  float* Srow = g_S + (size_t)row * SST;
  const float* pxy = g_pxy + (size_t)row * 104;
  const bool cls = (n == 0);
  const int xcol = cls ? 0 : (n - 1) % 24;
  const int yrow = cls ? 0 : (n - 1) / 24;

  float pxl = 0.f, pyl = 0.f;
  if (lane < 24) {
    pxl = cls ? pxy[0] : pxy[25 + lane - xcol];
    pyl = cls ? pxy[52] : pxy[52 + 25 + lane - yrow];
  }
  const float l0 = (Srow[0] + pxy[0] + pxy[52]) * SCALE_;
  float mx = l0;
  float lg[24];
#pragma unroll
  for (int k = 0; k < 24; k++) {
    float pyk = __shfl_sync(0xffffffffu, pyl, k);
    float s = -1e30f;
    if (lane < 24) s = (Srow[1 + 24 * k + lane] + pxl + pyk) * SCALE_;
    lg[k] = s;
    mx = fmaxf(mx, s);
  }
#pragma unroll
  for (int o = 16; o; o >>= 1) mx = fmaxf(mx, __shfl_xor_sync(0xffffffffu, mx, o));

  float colsum = 0.f, total = 0.f, binyreg = 0.f;
  const float e0 = __expf(l0 - mx);
#pragma unroll
  for (int k = 0; k < 24; k++) {
    float e = 0.f;
    if (lane < 24) {
      e = __expf(lg[k] - mx);
      Srow[1 + 24 * k + lane] = e;
    }
    colsum += e;
    float rs = e;
#pragma unroll
    for (int o = 16; o; o >>= 1) rs += __shfl_xor_sync(0xffffffffu, rs, o);
    total += rs;
    if (lane == k) binyreg = rs;
  }
  if (lane == 0) Srow[0] = e0;
  Srow[577 + lane] = 0.f;  // zero-pad cols 577..608 for the AV mma
  total += e0;
  if (lane == 0) g_rowsum[row] = total;

  st[w][lane] = colsum;
  st[w][32 + lane] = binyreg;
  __syncwarp();
  float* brow = g_bins + (size_t)row * 104;
  for (int t = lane; t < 104; t += 32) {
    float v = 0.f;
    if (cls) {
      if (t == 0 || t == 52) v = total;
    } else if (t == 0 || t == 52) {
      v = e0;
    } else if (t < 52) {
      int c = t - 25 + xcol;
      if (c >= 0 && c < 24) v = st[w][c];
    } else {
      int k = (t - 52) - 25 + yrow;
      if (k >= 0 && k < 24) v = st[w][32 + k];
    }
    brow[t] = v;
  }
}

// ---------------- AV via fp16 mma + bias-mma + normalize ----------------
// main: As[128][20] P tile, Bs[64][20] vT tile.
// bias: bxs/bys[128][36], exs/eys[32][36], invs[128].
#define AV_SMEM 46592
__global__ __launch_bounds__(256)
void av_mma_kernel(const float* __restrict__ vxe, const float* __restrict__ vye) {
  extern __shared__ uint32_t dsm[];
  uint32_t(*As)[20] = (uint32_t(*)[20])dsm;               // [128][20]
  uint32_t(*Bs)[20] = (uint32_t(*)[20])(dsm + 2560);      // [64][20]
  const int bh = blockIdx.y, row0 = blockIdx.x * 128;
  const int tid = threadIdx.x, lane = tid & 31, wid = tid >> 5;
  const int g = lane >> 2, tg = lane & 3;

  float acc[8][4];
#pragma unroll
  for (int i = 0; i < 8; i++)
#pragma unroll
    for (int j = 0; j < 4; j++) acc[i][j] = 0.f;

  const int lr = tid >> 1, lkf = (tid & 1) * 16, lkw = (tid & 1) * 8;
  const float* ap = g_S + ((size_t)bh * N_ + row0 + lr) * SST + lkf;
  const int vr = tid >> 2, vcf = (tid & 3) * 8, vcw = (tid & 3) * 4;
  const float* vp = g_vT + (size_t)bh * D_ * KTS + (size_t)vr * KTS + vcf;
  const int wr = wid * 16;

  for (int k0 = 0; k0 < 608; k0 += 32) {
    __syncthreads();
    {
      float4 a0 = *(const float4*)(ap + k0);
      float4 a1 = *(const float4*)(ap + k0 + 4);
      float4 a2 = *(const float4*)(ap + k0 + 8);
      float4 a3 = *(const float4*)(ap + k0 + 12);
      uint2 w0 = cvt4h(a0), w1 = cvt4h(a1), w2 = cvt4h(a2), w3 = cvt4h(a3);
      *(uint4*)&As[lr][lkw] = make_uint4(w0.x, w0.y, w1.x, w1.y);
      *(uint4*)&As[lr][lkw + 4] = make_uint4(w2.x, w2.y, w3.x, w3.y);
      float4 b0 = *(const float4*)(vp + k0);
      float4 b1 = *(const float4*)(vp + k0 + 4);
      uint2 u0 = cvt4h(b0), u1 = cvt4h(b1);
      *(uint4*)&Bs[vr][vcw] = make_uint4(u0.x, u0.y, u1.x, u1.y);
    }
    __syncthreads();
#pragma unroll
    for (int s = 0; s < 2; s++) {
      const int kw = s * 8;
      uint32_t a[4];
      a[0] = As[wr + g][kw + tg];
      a[1] = As[wr + g + 8][kw + tg];
      a[2] = As[wr + g][kw + tg + 4];
      a[3] = As[wr + g + 8][kw + tg + 4];
#pragma unroll
      for (int nt = 0; nt < 8; nt++) {
        uint32_t b0 = Bs[nt * 8 + g][kw + tg];
        uint32_t b1 = Bs[nt * 8 + g][kw + tg + 4];
        mmaf16(acc[nt], a, b0, b1);
      }
    }
  }
  __syncthreads();

  // ---- bias phase: bins (128x52) x emb^T (32x52) via fp16 mma (K pad 64) ----
  uint32_t* bxs = dsm;                          // [128][36]
  uint32_t* bys = dsm + 4608;                   // [128][36]
  uint32_t* exs = dsm + 9216;                   // [32][36]
  uint32_t* eys = dsm + 10368;                  // [32][36]
  float* invs = (float*)(dsm + 11520);          // [128]

  for (int f = tid; f < 128 * 32; f += 256) {
    int r = f >> 5, w = f & 31;
    int n = row0 + r;
    int t0 = 2 * w, t1 = 2 * w + 1;
    float vx0 = 0.f, vx1 = 0.f, vy0 = 0.f, vy1 = 0.f;
    if (n < N_) {
      const float* p = g_bins + ((size_t)bh * N_ + n) * 104;
      if (t0 < 52) { vx0 = p[t0]; vy0 = p[52 + t0]; }
      if (t1 < 52) { vx1 = p[t1]; vy1 = p[52 + t1]; }
    }
    bxs[r * 36 + w] = f2h2(vx0, vx1);
    bys[r * 36 + w] = f2h2(vy0, vy1);
  }
  for (int f = tid; f < 32 * 32; f += 256) {
    int c = f >> 5, w = f & 31;
    int t0 = 2 * w, t1 = 2 * w + 1;
    float ax0 = (t0 < 50) ? vxe[t0 * 32 + c] : 0.f;
    float ax1 = (t1 < 50) ? vxe[t1 * 32 + c] : 0.f;
    float ay0 = (t0 < 50) ? vye[t0 * 32 + c] : 0.f;
    float ay1 = (t1 < 50) ? vye[t1 * 32 + c] : 0.f;
    exs[c * 36 + w] = f2h2(ax0, ax1);
    eys[c * 36 + w] = f2h2(ay0, ay1);
  }
  for (int f = tid; f < 128; f += 256) {
    int n = row0 + f;
    invs[f] = (n < N_) ? 1.f / g_rowsum[(size_t)bh * N_ + n] : 1.f;
  }
  __syncthreads();

#pragma unroll
  for (int s = 0; s < 4; s++) {
    const int kw = s * 8;
    uint32_t ax[4], ay[4];
    ax[0] = bxs[(wr + g) * 36 + kw + tg];
    ax[1] = bxs[(wr + g + 8) * 36 + kw + tg];
    ax[2] = bxs[(wr + g) * 36 + kw + tg + 4];
    ax[3] = bxs[(wr + g + 8) * 36 + kw + tg + 4];
    ay[0] = bys[(wr + g) * 36 + kw + tg];
    ay[1] = bys[(wr + g + 8) * 36 + kw + tg];
    ay[2] = bys[(wr + g) * 36 + kw + tg + 4];
    ay[3] = bys[(wr + g + 8) * 36 + kw + tg + 4];
#pragma unroll
    for (int nt = 0; nt < 4; nt++) {
      uint32_t b0 = exs[(nt * 8 + g) * 36 + kw + tg];
      uint32_t b1 = exs[(nt * 8 + g) * 36 + kw + tg + 4];
      mmaf16(acc[nt], ax, b0, b1);
    }
#pragma unroll
    for (int nt = 0; nt < 4; nt++) {
      uint32_t b0 = eys[(nt * 8 + g) * 36 + kw + tg];
      uint32_t b1 = eys[(nt * 8 + g) * 36 + kw + tg + 4];
      mmaf16(acc[4 + nt], ay, b0, b1);
    }
  }

  // ---- normalize + store ----
  const float i0 = invs[wr + g], i1 = invs[wr + g + 8];
  const int b = bh / H_, h = bh % H_;
#pragma unroll
  for (int half = 0; half < 2; half++) {
    const int n = row0 + wr + g + half * 8;
    if (n >= N_) continue;
    const float inv = half ? i1 : i0;
    float* dst = g_ao + ((size_t)b * N_ + n) * C_ + h * D_ + 2 * tg;
#pragma unroll
    for (int nt = 0; nt < 8; nt++)
      *(float2*)(dst + nt * 8) = make_float2(acc[nt][half * 2] * inv,
                                             acc[nt][half * 2 + 1] * inv);
  }
}

// ---------------- launch ----------------
extern "C" void kernel_launch(void* const* d_in, const int* in_sizes, int n_in,
                              void* d_out, int out_size) {
  const float* x = (const float*)d_in[0];
  const float* qkv_w = (const float*)d_in[1];
  const float* proj_w = (const float*)d_in[2];
  const float* qxe = (const float*)d_in[3];
  const float* qye = (const float*)d_in[4];
  const float* vxe = (const float*)d_in[5];
  const float* vye = (const float*)d_in[6];
  float* out = (float*)d_out;

  cudaFuncSetAttribute(av_mma_kernel, cudaFuncAttributeMaxDynamicSharedMemorySize,
                       AV_SMEM);

  // QKV projection (fp16 tensor cores)
  mma_gemm_kernel<0><<<dim3(18, 73), 256>>>(x, qkv_w, nullptr);

  pxpy_kernel<<<dim3(10, BH_), 256>>>(qxe, qye);

  // scores (fp16 tensor cores)
  scores_mma_kernel<<<dim3(5, 5, BH_), 256>>>();

  softmax_kernel<<<(BH_ * N_ + 7) / 8, 256>>>();

  // AV + bias (fp16 tensor cores)
  av_mma_kernel<<<dim3(5, BH_), 256, AV_SMEM>>>(vxe, vye);

  // Output projection (fp16 tensor cores)
  mma_gemm_kernel<1><<<dim3(6, 73), 256>>>(nullptr, proj_w, out);
}

// round 12
// speedup vs baseline: 1.5756x; 1.0991x over previous
#include <cuda_runtime.h>
#include <cuda_fp16.h>
#include <cstdint>

#define B_ 16
#define N_ 577
#define H_ 12
#define D_ 64
#define C_ 768
#define BH_ 192
#define M_ 9232
#define KTS 640       // vT row stride (zero-padded cols 577..639)
#define SST 640       // score row stride
#define SCALE_ 0.125f

// ---------------- device scratch (zero-initialized; no cudaMalloc) --------
__device__ __half g_q[BH_ * N_ * D_];                 // (bh, n, d) fp16
__device__ __half g_k[BH_ * N_ * D_];                 // (bh, n, d) fp16
__device__ __half g_vT[BH_ * D_ * KTS];               // (bh, d, m) fp16, 0-pad
__device__ __half g_S[(size_t)(BH_ * N_ + 64) * SST]; // scores/exp(P), fp16
__device__ float g_pxy[BH_ * N_ * 104];               // px[0:52), py[52:104)
__device__ float g_bins[BH_ * N_ * 104];              // binx, biny
__device__ float g_rowsum[BH_ * N_ + 64];
__device__ float g_ao[M_ * C_];                       // attention out (b*n, c)

// ---------------- fp16 mma helpers (base sm_103 target) ----------------
__device__ __forceinline__ uint32_t f2h2(float lo, float hi) {
  __half2 h = __floats2half2_rn(lo, hi);
  return *reinterpret_cast<uint32_t*>(&h);
}
__device__ __forceinline__ uint2 cvt4h(float4 v) {
  return make_uint2(f2h2(v.x, v.y), f2h2(v.z, v.w));
}
__device__ __forceinline__ void mmaf16(float* d, const uint32_t* a,
                                       uint32_t b0, uint32_t b1) {
  asm volatile(
      "mma.sync.aligned.m16n8k16.row.col.f32.f16.f16.f32 "
      "{%0,%1,%2,%3}, {%4,%5,%6,%7}, {%8,%9}, {%0,%1,%2,%3};"
      : "+f"(d[0]), "+f"(d[1]), "+f"(d[2]), "+f"(d[3])
      : "r"(a[0]), "r"(a[1]), "r"(a[2]), "r"(a[3]), "r"(b0), "r"(b1));
}

// ======== fp16 mma GEMM: C[m,c] = sum_k A[m,k] * W[c,k] ========
// MODE 0: A = x, store q/k fp16 natural + vT fp16 transposed
// MODE 1: A = g_ao, row-major fp32 store into out
template <int MODE>
__global__ __launch_bounds__(256)
void mma_gemm_kernel(const float* __restrict__ Ain, const float* __restrict__ W,
                     float* __restrict__ out) {
  __shared__ uint32_t As[128][20];
  __shared__ uint32_t Bs[128][20];
  const float* A = (MODE == 0) ? Ain : (const float*)g_ao;
  const int row0 = blockIdx.y * 128, col0 = blockIdx.x * 128;
  const int tid = threadIdx.x, lane = tid & 31, wid = tid >> 5;
  const int warpM = wid & 3, warpN = wid >> 2;
  const int g = lane >> 2, tg = lane & 3;

  float acc[16][4];
#pragma unroll
  for (int i = 0; i < 16; i++)
#pragma unroll
    for (int j = 0; j < 4; j++) acc[i][j] = 0.f;

  const int lr = tid >> 1;
  const int lkf = (tid & 1) * 16;
  const int lkw = (tid & 1) * 8;
  const bool aval = (row0 + lr) < M_;
  const float* ap = A + (size_t)(row0 + lr) * C_ + lkf;
  const float* bp = W + (size_t)(col0 + lr) * C_ + lkf;

  for (int k0 = 0; k0 < C_; k0 += 32) {
    __syncthreads();
    {
      float4 a0, a1, a2, a3;
      if (aval) {
        a0 = *(const float4*)(ap + k0);
        a1 = *(const float4*)(ap + k0 + 4);
        a2 = *(const float4*)(ap + k0 + 8);
        a3 = *(const float4*)(ap + k0 + 12);
      } else {
        a0 = make_float4(0.f, 0.f, 0.f, 0.f);
        a1 = a0; a2 = a0; a3 = a0;
      }
      float4 b0 = *(const float4*)(bp + k0);
      float4 b1 = *(const float4*)(bp + k0 + 4);
      float4 b2 = *(const float4*)(bp + k0 + 8);
      float4 b3 = *(const float4*)(bp + k0 + 12);
      uint2 wa0 = cvt4h(a0), wa1 = cvt4h(a1), wa2 = cvt4h(a2), wa3 = cvt4h(a3);
      uint2 wb0 = cvt4h(b0), wb1 = cvt4h(b1), wb2 = cvt4h(b2), wb3 = cvt4h(b3);
      *(uint4*)&As[lr][lkw] = make_uint4(wa0.x, wa0.y, wa1.x, wa1.y);
      *(uint4*)&As[lr][lkw + 4] = make_uint4(wa2.x, wa2.y, wa3.x, wa3.y);
      *(uint4*)&Bs[lr][lkw] = make_uint4(wb0.x, wb0.y, wb1.x, wb1.y);
      *(uint4*)&Bs[lr][lkw + 4] = make_uint4(wb2.x, wb2.y, wb3.x, wb3.y);
    }
    __syncthreads();
#pragma unroll
    for (int s = 0; s < 2; s++) {
      const int kw = s * 8;
      uint32_t a[2][4];
#pragma unroll
      for (int mt = 0; mt < 2; mt++) {
        const int r = warpM * 32 + mt * 16;
        a[mt][0] = As[r + g][kw + tg];
        a[mt][1] = As[r + g + 8][kw + tg];
        a[mt][2] = As[r + g][kw + tg + 4];
        a[mt][3] = As[r + g + 8][kw + tg + 4];
      }
#pragma unroll
      for (int nt = 0; nt < 8; nt++) {
        const int c = warpN * 64 + nt * 8;
        uint32_t b0 = Bs[c + g][kw + tg];
        uint32_t b1 = Bs[c + g][kw + tg + 4];
        mmaf16(acc[nt], a[0], b0, b1);
        mmaf16(acc[8 + nt], a[1], b0, b1);
      }
    }
  }

  if (MODE == 1) {
#pragma unroll
    for (int mt = 0; mt < 2; mt++)
#pragma unroll
      for (int half = 0; half < 2; half++) {
        const int m = row0 + warpM * 32 + mt * 16 + g + half * 8;
        if (m >= M_) continue;
        float* dst = out + (size_t)m * C_ + col0 + warpN * 64 + 2 * tg;
#pragma unroll
        for (int nt = 0; nt < 8; nt++)
          *(float2*)(dst + nt * 8) = make_float2(acc[mt * 8 + nt][half * 2],
                                                 acc[mt * 8 + nt][half * 2 + 1]);
      }
  } else {
    const int cg = col0 + warpN * 64;
    const int which = cg / C_;          // 0=q 1=k 2=v
    const int h = (cg % C_) / D_;
#pragma unroll
    for (int mt = 0; mt < 2; mt++)
#pragma unroll
      for (int half = 0; half < 2; half++) {
        const int m = row0 + warpM * 32 + mt * 16 + g + half * 8;
        if (m >= M_) continue;
        const int b = m / N_, n = m % N_;
        const int bh = b * H_ + h;
        if (which == 2) {
          __half* vbase = g_vT + (size_t)bh * D_ * KTS + n;
          const int d0 = 2 * tg;
#pragma unroll
          for (int nt = 0; nt < 8; nt++) {
            vbase[(size_t)(d0 + nt * 8) * KTS] =
                __float2half(acc[mt * 8 + nt][half * 2]);
            vbase[(size_t)(d0 + nt * 8 + 1) * KTS] =
                __float2half(acc[mt * 8 + nt][half * 2 + 1]);
          }
        } else {
          __half* dst = (which == 0 ? g_q : g_k) + ((size_t)bh * N_ + n) * D_ + 2 * tg;
#pragma unroll
          for (int nt = 0; nt < 8; nt++)
            *(uint32_t*)(dst + nt * 8) =
                f2h2(acc[mt * 8 + nt][half * 2], acc[mt * 8 + nt][half * 2 + 1]);
        }
      }
  }
}

// ---------------- px/py projection (reads fp16 q) ----------------
__global__ __launch_bounds__(256)
void pxpy_kernel(const float* __restrict__ qxe, const float* __restrict__ qye) {
  __shared__ float qs[64][65];
  __shared__ float ex[50][33];
  __shared__ float ey[50][33];
  const int bh = blockIdx.y;
  const int row0 = blockIdx.x * 64;
  const int tid = threadIdx.x;
  for (int f = tid; f < 64 * 8; f += 256) {
    int r = f >> 3, c8 = (f & 7) << 3;
    int n = row0 + r;
    if (n < N_) {
      uint4 u = *(const uint4*)(g_q + ((size_t)bh * N_ + n) * D_ + c8);
      const __half2* hp = (const __half2*)&u;
#pragma unroll
      for (int j = 0; j < 4; j++) {
        float2 fv = __half22float2(hp[j]);
        qs[r][c8 + 2 * j] = fv.x;
        qs[r][c8 + 2 * j + 1] = fv.y;
      }
    } else {
#pragma unroll
      for (int j = 0; j < 8; j++) qs[r][c8 + j] = 0.f;
    }
  }
  for (int f = tid; f < 1600; f += 256) {
    ex[f >> 5][f & 31] = qxe[f];
    ey[f >> 5][f & 31] = qye[f];
  }
  __syncthreads();
  for (int idx = tid; idx < 64 * 50; idx += 256) {
    int r = idx / 50, t = idx % 50;
    float ax = 0.f, ay = 0.f;
#pragma unroll
    for (int d = 0; d < 32; d++) {
      ax += qs[r][d] * ex[t][d];
      ay += qs[r][32 + d] * ey[t][d];
    }
    int n = row0 + r;
    if (n < N_) {
      float* p = g_pxy + ((size_t)bh * N_ + n) * 104;
      p[t] = ax;
      p[52 + t] = ay;
    }
  }
}

// ---------------- scores via fp16 mma: S[bh,n,m] = q·k ----------------
// q/k already fp16: staging is a straight copy (no cvt).
__global__ __launch_bounds__(256)
void scores_mma_kernel() {
  __shared__ uint32_t As[128][36];
  __shared__ uint32_t Bs[128][36];
  const int bh = blockIdx.z;
  const int row0 = blockIdx.y * 128, col0 = blockIdx.x * 128;
  const int tid = threadIdx.x, lane = tid & 31, wid = tid >> 5;
  const int warpM = wid & 3, warpN = wid >> 2;
  const int g = lane >> 2, tg = lane & 3;

  float acc[16][4];
#pragma unroll
  for (int i = 0; i < 16; i++)
#pragma unroll
    for (int j = 0; j < 4; j++) acc[i][j] = 0.f;

  const int lr = tid >> 1;
  const int lkf = (tid & 1) * 32;    // half offset 0 / 32
  const int lkw = (tid & 1) * 16;    // word offset 0 / 16
  const bool aval = (row0 + lr) < N_;
  const bool bval = (col0 + lr) < N_;
  const __half* ap = g_q + ((size_t)bh * N_ + row0 + lr) * D_ + lkf;
  const __half* bp = g_k + ((size_t)bh * N_ + col0 + lr) * D_ + lkf;

  const uint4 zz = make_uint4(0u, 0u, 0u, 0u);
#pragma unroll
  for (int i = 0; i < 4; i++) {   // 4 x uint4 = 32 halves = 16 words
    uint4 va = aval ? *(const uint4*)(ap + i * 8) : zz;
    uint4 vb = bval ? *(const uint4*)(bp + i * 8) : zz;
    *(uint4*)&As[lr][lkw + i * 4] = va;
    *(uint4*)&Bs[lr][lkw + i * 4] = vb;
  }
  __syncthreads();

#pragma unroll
  for (int s = 0; s < 4; s++) {
    const int kw = s * 8;
    uint32_t a[2][4];
#pragma unroll
    for (int mt = 0; mt < 2; mt++) {
      const int r = warpM * 32 + mt * 16;
      a[mt][0] = As[r + g][kw + tg];
      a[mt][1] = As[r + g + 8][kw + tg];
      a[mt][2] = As[r + g][kw + tg + 4];
      a[mt][3] = As[r + g + 8][kw + tg + 4];
    }
#pragma unroll
    for (int nt = 0; nt < 8; nt++) {
      const int c = warpN * 64 + nt * 8;
      uint32_t b0 = Bs[c + g][kw + tg];
      uint32_t b1 = Bs[c + g][kw + tg + 4];
      mmaf16(acc[nt], a[0], b0, b1);
      mmaf16(acc[8 + nt], a[1], b0, b1);
    }
  }

#pragma unroll
  for (int mt = 0; mt < 2; mt++)
#pragma unroll
    for (int half = 0; half < 2; half++) {
      const int n = row0 + warpM * 32 + mt * 16 + g + half * 8;
      if (n >= N_) continue;
      __half* dst = g_S + ((size_t)bh * N_ + n) * SST + col0 + warpN * 64 + 2 * tg;
#pragma unroll
      for (int nt = 0; nt < 8; nt++)
        *(uint32_t*)(dst + nt * 8) =
            f2h2(acc[mt * 8 + nt][half * 2], acc[mt * 8 + nt][half * 2 + 1]);
    }
}

// ---------------- softmax + bias + analytic binning (fp16 S) ----------------
__global__ __launch_bounds__(256)
void softmax_kernel() {
  __shared__ float st[8][64];
  const int w = threadIdx.x >> 5, lane = threadIdx.x & 31;
  const int row = blockIdx.x * 8 + w;
  if (row >= BH_ * N_) return;
  const int n = row % N_;
  __half* Srow = g_S + (size_t)row * SST;
  const float* pxy = g_pxy + (size_t)row * 104;
  const bool cls = (n == 0);
  const int xcol = cls ? 0 : (n - 1) % 24;
  const int yrow = cls ? 0 : (n - 1) / 24;

  float pxl = 0.f, pyl = 0.f;
  if (lane < 24) {
    pxl = cls ? pxy[0] : pxy[25 + lane - xcol];
    pyl = cls ? pxy[52] : pxy[52 + 25 + lane - yrow];
  }
  const float l0 = (__half2float(Srow[0]) + pxy[0] + pxy[52]) * SCALE_;
  float mx = l0;
  float lg[24];
#pragma unroll
  for (int k = 0; k < 24; k++) {
    float pyk = __shfl_sync(0xffffffffu, pyl, k);
    float s = -1e30f;
    if (lane < 24)
      s = (__half2float(Srow[1 + 24 * k + lane]) + pxl + pyk) * SCALE_;
    lg[k] = s;
    mx = fmaxf(mx, s);
  }
#pragma unroll
  for (int o = 16; o; o >>= 1) mx = fmaxf(mx, __shfl_xor_sync(0xffffffffu, mx, o));

  float colsum = 0.f, total = 0.f, binyreg = 0.f;
  const float e0 = __expf(l0 - mx);
#pragma unroll
  for (int k = 0; k < 24; k++) {
    float e = 0.f;
    if (lane < 24) {
      e = __expf(lg[k] - mx);
      Srow[1 + 24 * k + lane] = __float2half(e);
    }
    colsum += e;
    float rs = e;
#pragma unroll
    for (int o = 16; o; o >>= 1) rs += __shfl_xor_sync(0xffffffffu, rs, o);
    total += rs;
    if (lane == k) binyreg = rs;
  }
  if (lane == 0) Srow[0] = __float2half(e0);
  Srow[577 + lane] = __float2half(0.f);  // zero-pad 577..608 for AV
  total += e0;
  if (lane == 0) g_rowsum[row] = total;

  st[w][lane] = colsum;
  st[w][32 + lane] = binyreg;
  __syncwarp();
  float* brow = g_bins + (size_t)row * 104;
  for (int t = lane; t < 104; t += 32) {
    float v = 0.f;
    if (cls) {
      if (t == 0 || t == 52) v = total;
    } else if (t == 0 || t == 52) {
      v = e0;
    } else if (t < 52) {
      int c = t - 25 + xcol;
      if (c >= 0 && c < 24) v = st[w][c];
    } else {
      int k = (t - 52) - 25 + yrow;
      if (k >= 0 && k < 24) v = st[w][32 + k];
    }
    brow[t] = v;
  }
}

// ---------------- AV via fp16 mma + bias-mma + normalize ----------------
// P and vT already fp16: staging is a straight copy (no cvt).
#define AV_SMEM 46592
__global__ __launch_bounds__(256)
void av_mma_kernel(const float* __restrict__ vxe, const float* __restrict__ vye) {
  extern __shared__ uint32_t dsm[];
  uint32_t(*As)[20] = (uint32_t(*)[20])dsm;               // [128][20]
  uint32_t(*Bs)[20] = (uint32_t(*)[20])(dsm + 2560);      // [64][20]
  const int bh = blockIdx.y, row0 = blockIdx.x * 128;
  const int tid = threadIdx.x, lane = tid & 31, wid = tid >> 5;
  const int g = lane >> 2, tg = lane & 3;

  float acc[8][4];
#pragma unroll
  for (int i = 0; i < 8; i++)
#pragma unroll
    for (int j = 0; j < 4; j++) acc[i][j] = 0.f;

  const int lr = tid >> 1, lkf = (tid & 1) * 16, lkw = (tid & 1) * 8;
  const __half* ap = g_S + ((size_t)bh * N_ + row0 + lr) * SST + lkf;
  const int vr = tid >> 2, vcf = (tid & 3) * 8, vcw = (tid & 3) * 4;
  const __half* vp = g_vT + (size_t)bh * D_ * KTS + (size_t)vr * KTS + vcf;
  const int wr = wid * 16;

  for (int k0 = 0; k0 < 608; k0 += 32) {
    __syncthreads();
    {
      *(uint4*)&As[lr][lkw] = *(const uint4*)(ap + k0);
      *(uint4*)&As[lr][lkw + 4] = *(const uint4*)(ap + k0 + 8);
      *(uint4*)&Bs[vr][vcw] = *(const uint4*)(vp + k0);
    }
    __syncthreads();
#pragma unroll
    for (int s = 0; s < 2; s++) {
      const int kw = s * 8;
      uint32_t a[4];
      a[0] = As[wr + g][kw + tg];
      a[1] = As[wr + g + 8][kw + tg];
      a[2] = As[wr + g][kw + tg + 4];
      a[3] = As[wr + g + 8][kw + tg + 4];
#pragma unroll
      for (int nt = 0; nt < 8; nt++) {
        uint32_t b0 = Bs[nt * 8 + g][kw + tg];
        uint32_t b1 = Bs[nt * 8 + g][kw + tg + 4];
        mmaf16(acc[nt], a, b0, b1);
      }
    }
  }
  __syncthreads();

  // ---- bias phase: bins (128x52) x emb^T (32x52) via fp16 mma ----
  uint32_t* bxs = dsm;                          // [128][36]
  uint32_t* bys = dsm + 4608;                   // [128][36]
  uint32_t* exs = dsm + 9216;                   // [32][36]
  uint32_t* eys = dsm + 10368;                  // [32][36]
  float* invs = (float*)(dsm + 11520);          // [128]

  for (int f = tid; f < 128 * 32; f += 256) {
    int r = f >> 5, w = f & 31;
    int n = row0 + r;
    int t0 = 2 * w, t1 = 2 * w + 1;
    float vx0 = 0.f, vx1 = 0.f, vy0 = 0.f, vy1 = 0.f;
    if (n < N_) {
      const float* p = g_bins + ((size_t)bh * N_ + n) * 104;
      if (t0 < 52) { vx0 = p[t0]; vy0 = p[52 + t0]; }
      if (t1 < 52) { vx1 = p[t1]; vy1 = p[52 + t1]; }
    }
    bxs[r * 36 + w] = f2h2(vx0, vx1);
    bys[r * 36 + w] = f2h2(vy0, vy1);
  }
  for (int f = tid; f < 32 * 32; f += 256) {
    int c = f >> 5, w = f & 31;
    int t0 = 2 * w, t1 = 2 * w + 1;
    float ax0 = (t0 < 50) ? vxe[t0 * 32 + c] : 0.f;
    float ax1 = (t1 < 50) ? vxe[t1 * 32 + c] : 0.f;
    float ay0 = (t0 < 50) ? vye[t0 * 32 + c] : 0.f;
    float ay1 = (t1 < 50) ? vye[t1 * 32 + c] : 0.f;
    exs[c * 36 + w] = f2h2(ax0, ax1);
    eys[c * 36 + w] = f2h2(ay0, ay1);
  }
  for (int f = tid; f < 128; f += 256) {
    int n = row0 + f;
    invs[f] = (n < N_) ? 1.f / g_rowsum[(size_t)bh * N_ + n] : 1.f;
  }
  __syncthreads();

#pragma unroll
  for (int s = 0; s < 4; s++) {
    const int kw = s * 8;
    uint32_t ax[4], ay[4];
    ax[0] = bxs[(wr + g) * 36 + kw + tg];
    ax[1] = bxs[(wr + g + 8) * 36 + kw + tg];
    ax[2] = bxs[(wr + g) * 36 + kw + tg + 4];
    ax[3] = bxs[(wr + g + 8) * 36 + kw + tg + 4];
    ay[0] = bys[(wr + g) * 36 + kw + tg];
    ay[1] = bys[(wr + g + 8) * 36 + kw + tg];
    ay[2] = bys[(wr + g) * 36 + kw + tg + 4];
    ay[3] = bys[(wr + g + 8) * 36 + kw + tg + 4];
#pragma unroll
    for (int nt = 0; nt < 4; nt++) {
      uint32_t b0 = exs[(nt * 8 + g) * 36 + kw + tg];
      uint32_t b1 = exs[(nt * 8 + g) * 36 + kw + tg + 4];
      mmaf16(acc[nt], ax, b0, b1);
    }
#pragma unroll
    for (int nt = 0; nt < 4; nt++) {
      uint32_t b0 = eys[(nt * 8 + g) * 36 + kw + tg];
      uint32_t b1 = eys[(nt * 8 + g) * 36 + kw + tg + 4];
      mmaf16(acc[4 + nt], ay, b0, b1);
    }
  }

  // ---- normalize + store ----
  const float i0 = invs[wr + g], i1 = invs[wr + g + 8];
  const int b = bh / H_, h = bh % H_;
#pragma unroll
  for (int half = 0; half < 2; half++) {
    const int n = row0 + wr + g + half * 8;
    if (n >= N_) continue;
    const float inv = half ? i1 : i0;
    float* dst = g_ao + ((size_t)b * N_ + n) * C_ + h * D_ + 2 * tg;
#pragma unroll
    for (int nt = 0; nt < 8; nt++)
      *(float2*)(dst + nt * 8) = make_float2(acc[nt][half * 2] * inv,
                                             acc[nt][half * 2 + 1] * inv);
  }
}

// ---------------- launch ----------------
extern "C" void kernel_launch(void* const* d_in, const int* in_sizes, int n_in,
                              void* d_out, int out_size) {
  const float* x = (const float*)d_in[0];
  const float* qkv_w = (const float*)d_in[1];
  const float* proj_w = (const float*)d_in[2];
  const float* qxe = (const float*)d_in[3];
  const float* qye = (const float*)d_in[4];
  const float* vxe = (const float*)d_in[5];
  const float* vye = (const float*)d_in[6];
  float* out = (float*)d_out;

  cudaFuncSetAttribute(av_mma_kernel, cudaFuncAttributeMaxDynamicSharedMemorySize,
                       AV_SMEM);

  // QKV projection (fp16 tensor cores, fp16 outputs)
  mma_gemm_kernel<0><<<dim3(18, 73), 256>>>(x, qkv_w, nullptr);

  pxpy_kernel<<<dim3(10, BH_), 256>>>(qxe, qye);

  // scores (fp16 in/out)
  scores_mma_kernel<<<dim3(5, 5, BH_), 256>>>();

  softmax_kernel<<<(BH_ * N_ + 7) / 8, 256>>>();

  // AV + bias (fp16 in)
  av_mma_kernel<<<dim3(5, BH_), 256, AV_SMEM>>>(vxe, vye);

  // Output projection (fp32 out)
  mma_gemm_kernel<1><<<dim3(6, 73), 256>>>(nullptr, proj_w, out);
}

// round 13
// speedup vs baseline: 1.7593x; 1.1166x over previous
#include <cuda_runtime.h>
#include <cuda_fp16.h>
#include <cstdint>

#define B_ 16
#define N_ 577
#define H_ 12
#define D_ 64
#define C_ 768
#define BH_ 192
#define M_ 9232
#define KTS 640       // vT row stride (zero-padded cols 577..639)
#define SST 640       // score row stride
#define SCALE_ 0.125f

// ---------------- device scratch (zero-initialized; no cudaMalloc) --------
__device__ __half g_xh[M_ * C_];                      // x in fp16
__device__ __half g_wqkv[3 * C_ * C_];                // qkv_w in fp16
__device__ __half g_wproj[C_ * C_];                   // proj_w in fp16
__device__ __half g_q[BH_ * N_ * D_];                 // (bh, n, d) fp16
__device__ __half g_k[BH_ * N_ * D_];                 // (bh, n, d) fp16
__device__ __half g_vT[BH_ * D_ * KTS];               // (bh, d, m) fp16, 0-pad
__device__ __half g_S[(size_t)(BH_ * N_ + 64) * SST]; // scores/exp(P), fp16
__device__ float g_pxy[BH_ * N_ * 104];               // px[0:52), py[52:104)
__device__ float g_bins[BH_ * N_ * 104];              // binx, biny
__device__ float g_rowsum[BH_ * N_ + 64];
__device__ __half g_ao[M_ * C_];                      // attention out, fp16

// ---------------- fp16 mma helpers (base sm_103 target) ----------------
__device__ __forceinline__ uint32_t f2h2(float lo, float hi) {
  __half2 h = __floats2half2_rn(lo, hi);
  return *reinterpret_cast<uint32_t*>(&h);
}
__device__ __forceinline__ void mmaf16(float* d, const uint32_t* a,
                                       uint32_t b0, uint32_t b1) {
  asm volatile(
      "mma.sync.aligned.m16n8k16.row.col.f32.f16.f16.f32 "
      "{%0,%1,%2,%3}, {%4,%5,%6,%7}, {%8,%9}, {%0,%1,%2,%3};"
      : "+f"(d[0]), "+f"(d[1]), "+f"(d[2]), "+f"(d[3])
      : "r"(a[0]), "r"(a[1]), "r"(a[2]), "r"(a[3]), "r"(b0), "r"(b1));
}

// ---------------- fp32 -> fp16 conversion prepass ----------------
__global__ __launch_bounds__(256)
void cvt_kernel(const float* __restrict__ src, __half* __restrict__ dst, int n8) {
  int i = blockIdx.x * blockDim.x + threadIdx.x;
  if (i >= n8) return;
  const float4 a = ((const float4*)src)[2 * i];
  const float4 b = ((const float4*)src)[2 * i + 1];
  ((uint4*)dst)[i] = make_uint4(f2h2(a.x, a.y), f2h2(a.z, a.w),
                                f2h2(b.x, b.y), f2h2(b.z, b.w));
}

// ======== fp16 mma GEMM: C[m,c] = sum_k A[m,k] * W[c,k] (all-fp16 in) ======
// MODE 0: A = g_xh, W = g_wqkv, store q/k natural + vT transposed (fp16)
// MODE 1: A = g_ao, W = g_wproj, row-major fp32 store into out
template <int MODE>
__global__ __launch_bounds__(256)
void mma_gemm_kernel(float* __restrict__ out) {
  __shared__ uint32_t As[128][20];
  __shared__ uint32_t Bs[128][20];
  const __half* A = (MODE == 0) ? g_xh : g_ao;
  const __half* W = (MODE == 0) ? g_wqkv : g_wproj;
  const int row0 = blockIdx.y * 128, col0 = blockIdx.x * 128;
  const int tid = threadIdx.x, lane = tid & 31, wid = tid >> 5;
  const int warpM = wid & 3, warpN = wid >> 2;
  const int g = lane >> 2, tg = lane & 3;

  float acc[16][4];
#pragma unroll
  for (int i = 0; i < 16; i++)
#pragma unroll
    for (int j = 0; j < 4; j++) acc[i][j] = 0.f;

  const int lr = tid >> 1;           // 0..127
  const int lkf = (tid & 1) * 16;    // half offset 0 / 16
  const int lkw = (tid & 1) * 8;     // word offset 0 / 8
  const bool aval = (row0 + lr) < M_;
  const __half* ap = A + (size_t)(row0 + lr) * C_ + lkf;
  const __half* bp = W + (size_t)(col0 + lr) * C_ + lkf;
  const uint4 zz = make_uint4(0u, 0u, 0u, 0u);

  for (int k0 = 0; k0 < C_; k0 += 32) {
    __syncthreads();
    {
      uint4 va0 = aval ? *(const uint4*)(ap + k0) : zz;
      uint4 va1 = aval ? *(const uint4*)(ap + k0 + 8) : zz;
      uint4 vb0 = *(const uint4*)(bp + k0);
      uint4 vb1 = *(const uint4*)(bp + k0 + 8);
      *(uint4*)&As[lr][lkw] = va0;
      *(uint4*)&As[lr][lkw + 4] = va1;
      *(uint4*)&Bs[lr][lkw] = vb0;
      *(uint4*)&Bs[lr][lkw + 4] = vb1;
    }
    __syncthreads();
#pragma unroll
    for (int s = 0; s < 2; s++) {
      const int kw = s * 8;
      uint32_t a[2][4];
#pragma unroll
      for (int mt = 0; mt < 2; mt++) {
        const int r = warpM * 32 + mt * 16;
        a[mt][0] = As[r + g][kw + tg];
        a[mt][1] = As[r + g + 8][kw + tg];
        a[mt][2] = As[r + g][kw + tg + 4];
        a[mt][3] = As[r + g + 8][kw + tg + 4];
      }
#pragma unroll
      for (int nt = 0; nt < 8; nt++) {
        const int c = warpN * 64 + nt * 8;
        uint32_t b0 = Bs[c + g][kw + tg];
        uint32_t b1 = Bs[c + g][kw + tg + 4];
        mmaf16(acc[nt], a[0], b0, b1);
        mmaf16(acc[8 + nt], a[1], b0, b1);
      }
    }
  }

  if (MODE == 1) {
#pragma unroll
    for (int mt = 0; mt < 2; mt++)
#pragma unroll
      for (int half = 0; half < 2; half++) {
        const int m = row0 + warpM * 32 + mt * 16 + g + half * 8;
        if (m >= M_) continue;
        float* dst = out + (size_t)m * C_ + col0 + warpN * 64 + 2 * tg;
#pragma unroll
        for (int nt = 0; nt < 8; nt++)
          *(float2*)(dst + nt * 8) = make_float2(acc[mt * 8 + nt][half * 2],
                                                 acc[mt * 8 + nt][half * 2 + 1]);
      }
  } else {
    const int cg = col0 + warpN * 64;
    const int which = cg / C_;          // 0=q 1=k 2=v
    const int h = (cg % C_) / D_;
#pragma unroll
    for (int mt = 0; mt < 2; mt++)
#pragma unroll
      for (int half = 0; half < 2; half++) {
        const int m = row0 + warpM * 32 + mt * 16 + g + half * 8;
        if (m >= M_) continue;
        const int b = m / N_, n = m % N_;
        const int bh = b * H_ + h;
        if (which == 2) {
          __half* vbase = g_vT + (size_t)bh * D_ * KTS + n;
          const int d0 = 2 * tg;
#pragma unroll
          for (int nt = 0; nt < 8; nt++) {
            vbase[(size_t)(d0 + nt * 8) * KTS] =
                __float2half(acc[mt * 8 + nt][half * 2]);
            vbase[(size_t)(d0 + nt * 8 + 1) * KTS] =
                __float2half(acc[mt * 8 + nt][half * 2 + 1]);
          }
        } else {
          __half* dst = (which == 0 ? g_q : g_k) + ((size_t)bh * N_ + n) * D_ + 2 * tg;
#pragma unroll
          for (int nt = 0; nt < 8; nt++)
            *(uint32_t*)(dst + nt * 8) =
                f2h2(acc[mt * 8 + nt][half * 2], acc[mt * 8 + nt][half * 2 + 1]);
        }
      }
  }
}

// ---------------- px/py projection (reads fp16 q) ----------------
__global__ __launch_bounds__(256)
void pxpy_kernel(const float* __restrict__ qxe, const float* __restrict__ qye) {
  __shared__ float qs[64][65];
  __shared__ float ex[50][33];
  __shared__ float ey[50][33];
  const int bh = blockIdx.y;
  const int row0 = blockIdx.x * 64;
  const int tid = threadIdx.x;
  for (int f = tid; f < 64 * 8; f += 256) {
    int r = f >> 3, c8 = (f & 7) << 3;
    int n = row0 + r;
    if (n < N_) {
      uint4 u = *(const uint4*)(g_q + ((size_t)bh * N_ + n) * D_ + c8);
      const __half2* hp = (const __half2*)&u;
#pragma unroll
      for (int j = 0; j < 4; j++) {
        float2 fv = __half22float2(hp[j]);
        qs[r][c8 + 2 * j] = fv.x;
        qs[r][c8 + 2 * j + 1] = fv.y;
      }
    } else {
#pragma unroll
      for (int j = 0; j < 8; j++) qs[r][c8 + j] = 0.f;
    }
  }
  for (int f = tid; f < 1600; f += 256) {
    ex[f >> 5][f & 31] = qxe[f];
    ey[f >> 5][f & 31] = qye[f];
  }
  __syncthreads();
  for (int idx = tid; idx < 64 * 50; idx += 256) {
    int r = idx / 50, t = idx % 50;
    float ax = 0.f, ay = 0.f;
#pragma unroll
    for (int d = 0; d < 32; d++) {
      ax += qs[r][d] * ex[t][d];
      ay += qs[r][32 + d] * ey[t][d];
    }
    int n = row0 + r;
    if (n < N_) {
      float* p = g_pxy + ((size_t)bh * N_ + n) * 104;
      p[t] = ax;
      p[52 + t] = ay;
    }
  }
}

// ---------------- scores via fp16 mma: S[bh,n,m] = q·k ----------------
__global__ __launch_bounds__(256)
void scores_mma_kernel() {
  __shared__ uint32_t As[128][36];
  __shared__ uint32_t Bs[128][36];
  const int bh = blockIdx.z;
  const int row0 = blockIdx.y * 128, col0 = blockIdx.x * 128;
  const int tid = threadIdx.x, lane = tid & 31, wid = tid >> 5;
  const int warpM = wid & 3, warpN = wid >> 2;
  const int g = lane >> 2, tg = lane & 3;

  float acc[16][4];
#pragma unroll
  for (int i = 0; i < 16; i++)
#pragma unroll
    for (int j = 0; j < 4; j++) acc[i][j] = 0.f;

  const int lr = tid >> 1;
  const int lkf = (tid & 1) * 32;    // half offset 0 / 32
  const int lkw = (tid & 1) * 16;    // word offset 0 / 16
  const bool aval = (row0 + lr) < N_;
  const bool bval = (col0 + lr) < N_;
  const __half* ap = g_q + ((size_t)bh * N_ + row0 + lr) * D_ + lkf;
  const __half* bp = g_k + ((size_t)bh * N_ + col0 + lr) * D_ + lkf;

  const uint4 zz = make_uint4(0u, 0u, 0u, 0u);
#pragma unroll
  for (int i = 0; i < 4; i++) {   // 4 x uint4 = 32 halves = 16 words
    uint4 va = aval ? *(const uint4*)(ap + i * 8) : zz;
    uint4 vb = bval ? *(const uint4*)(bp + i * 8) : zz;
    *(uint4*)&As[lr][lkw + i * 4] = va;
    *(uint4*)&Bs[lr][lkw + i * 4] = vb;
  }
  __syncthreads();

#pragma unroll
  for (int s = 0; s < 4; s++) {
    const int kw = s * 8;
    uint32_t a[2][4];
#pragma unroll
    for (int mt = 0; mt < 2; mt++) {
      const int r = warpM * 32 + mt * 16;
      a[mt][0] = As[r + g][kw + tg];
      a[mt][1] = As[r + g + 8][kw + tg];
      a[mt][2] = As[r + g][kw + tg + 4];
      a[mt][3] = As[r + g + 8][kw + tg + 4];
    }
#pragma unroll
    for (int nt = 0; nt < 8; nt++) {
      const int c = warpN * 64 + nt * 8;
      uint32_t b0 = Bs[c + g][kw + tg];
      uint32_t b1 = Bs[c + g][kw + tg + 4];
      mmaf16(acc[nt], a[0], b0, b1);
      mmaf16(acc[8 + nt], a[1], b0, b1);
    }
  }

#pragma unroll
  for (int mt = 0; mt < 2; mt++)
#pragma unroll
    for (int half = 0; half < 2; half++) {
      const int n = row0 + warpM * 32 + mt * 16 + g + half * 8;
      if (n >= N_) continue;
      __half* dst = g_S + ((size_t)bh * N_ + n) * SST + col0 + warpN * 64 + 2 * tg;
#pragma unroll
      for (int nt = 0; nt < 8; nt++)
        *(uint32_t*)(dst + nt * 8) =
            f2h2(acc[mt * 8 + nt][half * 2], acc[mt * 8 + nt][half * 2 + 1]);
    }
}

// ---------------- softmax + bias + analytic binning (fp16 S) ----------------
__global__ __launch_bounds__(256)
void softmax_kernel() {
  __shared__ float st[8][64];
  const int w = threadIdx.x >> 5, lane = threadIdx.x & 31;
  const int row = blockIdx.x * 8 + w;
  if (row >= BH_ * N_) return;
  const int n = row % N_;
  __half* Srow = g_S + (size_t)row * SST;
  const float* pxy = g_pxy + (size_t)row * 104;
  const bool cls = (n == 0);
  const int xcol = cls ? 0 : (n - 1) % 24;
  const int yrow = cls ? 0 : (n - 1) / 24;

  float pxl = 0.f, pyl = 0.f;
  if (lane < 24) {
    pxl = cls ? pxy[0] : pxy[25 + lane - xcol];
    pyl = cls ? pxy[52] : pxy[52 + 25 + lane - yrow];
  }
  const float l0 = (__half2float(Srow[0]) + pxy[0] + pxy[52]) * SCALE_;
  float mx = l0;
  float lg[24];
#pragma unroll
  for (int k = 0; k < 24; k++) {
    float pyk = __shfl_sync(0xffffffffu, pyl, k);
    float s = -1e30f;
    if (lane < 24)
      s = (__half2float(Srow[1 + 24 * k + lane]) + pxl + pyk) * SCALE_;
    lg[k] = s;
    mx = fmaxf(mx, s);
  }
#pragma unroll
  for (int o = 16; o; o >>= 1) mx = fmaxf(mx, __shfl_xor_sync(0xffffffffu, mx, o));

  float colsum = 0.f, total = 0.f, binyreg = 0.f;
  const float e0 = __expf(l0 - mx);
#pragma unroll
  for (int k = 0; k < 24; k++) {
    float e = 0.f;
    if (lane < 24) {
      e = __expf(lg[k] - mx);
      Srow[1 + 24 * k + lane] = __float2half(e);
    }
    colsum += e;
    float rs = e;
#pragma unroll
    for (int o = 16; o; o >>= 1) rs += __shfl_xor_sync(0xffffffffu, rs, o);
    total += rs;
    if (lane == k) binyreg = rs;
  }
  if (lane == 0) Srow[0] = __float2half(e0);
  Srow[577 + lane] = __float2half(0.f);
  total += e0;
  if (lane == 0) g_rowsum[row] = total;

  st[w][lane] = colsum;
  st[w][32 + lane] = binyreg;
  __syncwarp();
  float* brow = g_bins + (size_t)row * 104;
  for (int t = lane; t < 104; t += 32) {
    float v = 0.f;
    if (cls) {
      if (t == 0 || t == 52) v = total;
    } else if (t == 0 || t == 52) {
      v = e0;
    } else if (t < 52) {
      int c = t - 25 + xcol;
      if (c >= 0 && c < 24) v = st[w][c];
    } else {
      int k = (t - 52) - 25 + yrow;
      if (k >= 0 && k < 24) v = st[w][32 + k];
    }
    brow[t] = v;
  }
}

// ---------------- AV via fp16 mma + bias-mma + normalize ----------------
#define AV_SMEM 46592
__global__ __launch_bounds__(256)
void av_mma_kernel(const float* __restrict__ vxe, const float* __restrict__ vye) {
  extern __shared__ uint32_t dsm[];
  uint32_t(*As)[20] = (uint32_t(*)[20])dsm;               // [128][20]
  uint32_t(*Bs)[20] = (uint32_t(*)[20])(dsm + 2560);      // [64][20]
  const int bh = blockIdx.y, row0 = blockIdx.x * 128;
  const int tid = threadIdx.x, lane = tid & 31, wid = tid >> 5;
  const int g = lane >> 2, tg = lane & 3;

  float acc[8][4];
#pragma unroll
  for (int i = 0; i < 8; i++)
#pragma unroll
    for (int j = 0; j < 4; j++) acc[i][j] = 0.f;

  const int lr = tid >> 1, lkf = (tid & 1) * 16, lkw = (tid & 1) * 8;
  const __half* ap = g_S + ((size_t)bh * N_ + row0 + lr) * SST + lkf;
  const int vr = tid >> 2, vcf = (tid & 3) * 8, vcw = (tid & 3) * 4;
  const __half* vp = g_vT + (size_t)bh * D_ * KTS + (size_t)vr * KTS + vcf;
  const int wr = wid * 16;

  for (int k0 = 0; k0 < 608; k0 += 32) {
    __syncthreads();
    {
      *(uint4*)&As[lr][lkw] = *(const uint4*)(ap + k0);
      *(uint4*)&As[lr][lkw + 4] = *(const uint4*)(ap + k0 + 8);
      *(uint4*)&Bs[vr][vcw] = *(const uint4*)(vp + k0);
    }
    __syncthreads();
#pragma unroll
    for (int s = 0; s < 2; s++) {
      const int kw = s * 8;
      uint32_t a[4];
      a[0] = As[wr + g][kw + tg];
      a[1] = As[wr + g + 8][kw + tg];
      a[2] = As[wr + g][kw + tg + 4];
      a[3] = As[wr + g + 8][kw + tg + 4];
#pragma unroll
      for (int nt = 0; nt < 8; nt++) {
        uint32_t b0 = Bs[nt * 8 + g][kw + tg];
        uint32_t b1 = Bs[nt * 8 + g][kw + tg + 4];
        mmaf16(acc[nt], a, b0, b1);
      }
    }
  }
  __syncthreads();

  // ---- bias phase: bins (128x52) x emb^T (32x52) via fp16 mma ----
  uint32_t* bxs = dsm;                          // [128][36]
  uint32_t* bys = dsm + 4608;                   // [128][36]
  uint32_t* exs = dsm + 9216;                   // [32][36]
  uint32_t* eys = dsm + 10368;                  // [32][36]
  float* invs = (float*)(dsm + 11520);          // [128]

  for (int f = tid; f < 128 * 32; f += 256) {
    int r = f >> 5, w = f & 31;
    int n = row0 + r;
    int t0 = 2 * w, t1 = 2 * w + 1;
    float vx0 = 0.f, vx1 = 0.f, vy0 = 0.f, vy1 = 0.f;
    if (n < N_) {
      const float* p = g_bins + ((size_t)bh * N_ + n) * 104;
      if (t0 < 52) { vx0 = p[t0]; vy0 = p[52 + t0]; }
      if (t1 < 52) { vx1 = p[t1]; vy1 = p[52 + t1]; }
    }
    bxs[r * 36 + w] = f2h2(vx0, vx1);
    bys[r * 36 + w] = f2h2(vy0, vy1);
  }
  for (int f = tid; f < 32 * 32; f += 256) {
    int c = f >> 5, w = f & 31;
    int t0 = 2 * w, t1 = 2 * w + 1;
    float ax0 = (t0 < 50) ? vxe[t0 * 32 + c] : 0.f;
    float ax1 = (t1 < 50) ? vxe[t1 * 32 + c] : 0.f;
    float ay0 = (t0 < 50) ? vye[t0 * 32 + c] : 0.f;
    float ay1 = (t1 < 50) ? vye[t1 * 32 + c] : 0.f;
    exs[c * 36 + w] = f2h2(ax0, ax1);
    eys[c * 36 + w] = f2h2(ay0, ay1);
  }
  for (int f = tid; f < 128; f += 256) {
    int n = row0 + f;
    invs[f] = (n < N_) ? 1.f / g_rowsum[(size_t)bh * N_ + n] : 1.f;
  }
  __syncthreads();

#pragma unroll
  for (int s = 0; s < 4; s++) {
    const int kw = s * 8;
    uint32_t ax[4], ay[4];
    ax[0] = bxs[(wr + g) * 36 + kw + tg];
    ax[1] = bxs[(wr + g + 8) * 36 + kw + tg];
    ax[2] = bxs[(wr + g) * 36 + kw + tg + 4];
    ax[3] = bxs[(wr + g + 8) * 36 + kw + tg + 4];
    ay[0] = bys[(wr + g) * 36 + kw + tg];
    ay[1] = bys[(wr + g + 8) * 36 + kw + tg];
    ay[2] = bys[(wr + g) * 36 + kw + tg + 4];
    ay[3] = bys[(wr + g + 8) * 36 + kw + tg + 4];
#pragma unroll
    for (int nt = 0; nt < 4; nt++) {
      uint32_t b0 = exs[(nt * 8 + g) * 36 + kw + tg];
      uint32_t b1 = exs[(nt * 8 + g) * 36 + kw + tg + 4];
      mmaf16(acc[nt], ax, b0, b1);
    }
#pragma unroll
    for (int nt = 0; nt < 4; nt++) {
      uint32_t b0 = eys[(nt * 8 + g) * 36 + kw + tg];
      uint32_t b1 = eys[(nt * 8 + g) * 36 + kw + tg + 4];
      mmaf16(acc[4 + nt], ay, b0, b1);
    }
  }

  // ---- normalize + store (fp16 ao) ----
  const float i0 = invs[wr + g], i1 = invs[wr + g + 8];
  const int b = bh / H_, h = bh % H_;
#pragma unroll
  for (int half = 0; half < 2; half++) {
    const int n = row0 + wr + g + half * 8;
    if (n >= N_) continue;
    const float inv = half ? i1 : i0;
    __half* dst = g_ao + ((size_t)b * N_ + n) * C_ + h * D_ + 2 * tg;
#pragma unroll
    for (int nt = 0; nt < 8; nt++)
      *(uint32_t*)(dst + nt * 8) =
          f2h2(acc[nt][half * 2] * inv, acc[nt][half * 2 + 1] * inv);
  }
}

// ---------------- launch ----------------
extern "C" void kernel_launch(void* const* d_in, const int* in_sizes, int n_in,
                              void* d_out, int out_size) {
  const float* x = (const float*)d_in[0];
  const float* qkv_w = (const float*)d_in[1];
  const float* proj_w = (const float*)d_in[2];
  const float* qxe = (const float*)d_in[3];
  const float* qye = (const float*)d_in[4];
  const float* vxe = (const float*)d_in[5];
  const float* vye = (const float*)d_in[6];
  float* out = (float*)d_out;

  cudaFuncSetAttribute(av_mma_kernel, cudaFuncAttributeMaxDynamicSharedMemorySize,
                       AV_SMEM);

  // fp32 -> fp16 conversion prepass
  __half* d_xh = nullptr;
  __half* d_wqkv = nullptr;
  __half* d_wproj = nullptr;
  cudaGetSymbolAddress((void**)&d_xh, g_xh);
  cudaGetSymbolAddress((void**)&d_wqkv, g_wqkv);
  cudaGetSymbolAddress((void**)&d_wproj, g_wproj);
  cvt_kernel<<<(M_ * C_ / 8 + 255) / 256, 256>>>(x, d_xh, M_ * C_ / 8);
  cvt_kernel<<<(3 * C_ * C_ / 8 + 255) / 256, 256>>>(qkv_w, d_wqkv, 3 * C_ * C_ / 8);
  cvt_kernel<<<(C_ * C_ / 8 + 255) / 256, 256>>>(proj_w, d_wproj, C_ * C_ / 8);

  // QKV projection (fp16 in/out)
  mma_gemm_kernel<0><<<dim3(18, 73), 256>>>(nullptr);

  pxpy_kernel<<<dim3(10, BH_), 256>>>(qxe, qye);

  // scores (fp16 in/out)
  scores_mma_kernel<<<dim3(5, 5, BH_), 256>>>();

  softmax_kernel<<<(BH_ * N_ + 7) / 8, 256>>>();

  // AV + bias (fp16 in/out)
  av_mma_kernel<<<dim3(5, BH_), 256, AV_SMEM>>>(vxe, vye);

  // Output projection (fp16 in, fp32 out)
  mma_gemm_kernel<1><<<dim3(6, 73), 256>>>(out);
}